// round 3
// baseline (speedup 1.0000x reference)
#include <cuda_runtime.h>

// SwinV2 shifted-window attention, B=16, H=W=64, C=256, heads=8, hd=32,
// window 8x8, shift 4x4  ->  1024 windows x 64 tokens.
//
// Round 3: pre-converted tf32 operands + cp.async 3-stage pipelined GEMMs
// (M=128/CTA, 512 thr), attention inner loops on packed fma.rn.f32x2.

#define NWIN   1024
#define NTOK   64
#define CDIM   256
#define NHEAD  8
#define HD     32

typedef unsigned long long u64;

// -------- scratch (device globals; no allocation) --------
__device__ float    g_q  [NWIN * NHEAD * NTOK * HD];
__device__ float    g_k  [NWIN * NHEAD * NTOK * HD];
__device__ float    g_v  [NWIN * NHEAD * NTOK * HD];
__device__ unsigned g_ao [NWIN * NTOK * CDIM];        // attn out, tf32 bits
__device__ unsigned g_xtf[16 * 64 * 64 * CDIM];       // x in tf32 bits
__device__ unsigned g_wtf[4 * CDIM * CDIM];           // Wq,Wk,Wv,Wo tf32 bits
__device__ float    g_bias16[NHEAD * 225];
__device__ float    g_scale[NHEAD];

// -------- helpers --------
__device__ __forceinline__ unsigned f2tf(float f) {
    unsigned u;
    asm("cvt.rna.tf32.f32 %0, %1;" : "=r"(u) : "f"(f));
    return u;
}
__device__ __forceinline__ void mma8(float* c, const unsigned* a, const unsigned* b) {
    asm volatile("mma.sync.aligned.m16n8k8.row.col.f32.tf32.tf32.f32 "
                 "{%0,%1,%2,%3},{%4,%5,%6,%7},{%8,%9},{%0,%1,%2,%3};"
                 : "+f"(c[0]), "+f"(c[1]), "+f"(c[2]), "+f"(c[3])
                 : "r"(a[0]), "r"(a[1]), "r"(a[2]), "r"(a[3]),
                   "r"(b[0]), "r"(b[1]));
}
__device__ __forceinline__ void cp16(unsigned dst, const void* src) {
    asm volatile("cp.async.cg.shared.global [%0], [%1], 16;" :: "r"(dst), "l"(src));
}
__device__ __forceinline__ void cp_commit() {
    asm volatile("cp.async.commit_group;");
}
template<int N> __device__ __forceinline__ void cp_wait() {
    asm volatile("cp.async.wait_group %0;" :: "n"(N));
}
__device__ __forceinline__ void fma2(u64& d, u64 a, u64 b) {
    asm("fma.rn.f32x2 %0, %1, %2, %0;" : "+l"(d) : "l"(a), "l"(b));
}
__device__ __forceinline__ u64 add2(u64 a, u64 b) {
    u64 r;
    asm("add.rn.f32x2 %0, %1, %2;" : "=l"(r) : "l"(a), "l"(b));
    return r;
}
__device__ __forceinline__ void unpack2(u64 v, float& lo, float& hi) {
    unsigned ul, uh;
    asm("mov.b64 {%0,%1}, %2;" : "=r"(ul), "=r"(uh) : "l"(v));
    lo = __uint_as_float(ul);
    hi = __uint_as_float(uh);
}
__device__ __forceinline__ u64 bcast2(float f) {
    u64 r;
    unsigned u = __float_as_uint(f);
    asm("mov.b64 %0, {%1,%1};" : "=l"(r) : "r"(u));
    return r;
}

// -------- GEMM smem geometry --------
#define XCH   36                         // A chunk stride (mod 32 == 4)
#define WST   264                        // B chunk stride (mod 32 == 8)
#define XBUF  (128 * XCH)                // 4608 u32 per stage
#define WBUF  (32 * WST)                 // 8448 u32 per stage
#define NSTG  3
#define G_SMEM ((NSTG * (XBUF + WBUF) + 128) * 4)   // 157184 B

// ============================================================
// Kernel 0: continuous-position-bias MLP
// ============================================================
__global__ void swin_bias_kernel(const float* __restrict__ ls,
                                 const float* __restrict__ w1,
                                 const float* __restrict__ b1,
                                 const float* __restrict__ w2)
{
    __shared__ float part[16][8];
    const int t   = blockIdx.x;
    const int i   = t / 15;
    const int j   = t % 15;
    const int tid = threadIdx.x;
    const int warp = tid >> 5;
    const int lane = tid & 31;

    float rh = (float)(i - 7) * (8.0f / 7.0f);
    float rw = (float)(j - 7) * (8.0f / 7.0f);
    rh = copysignf(log2f(fabsf(rh) + 1.0f) * (1.0f / 3.0f), rh);
    rw = copysignf(log2f(fabsf(rw) + 1.0f) * (1.0f / 3.0f), rw);

    float hv = fmaxf(0.0f, rh * w1[tid] + rw * w1[512 + tid] + b1[tid]);

    float p[8];
#pragma unroll
    for (int h = 0; h < 8; ++h) p[h] = hv * w2[tid * 8 + h];
#pragma unroll
    for (int off = 16; off; off >>= 1)
#pragma unroll
        for (int h = 0; h < 8; ++h) p[h] += __shfl_xor_sync(0xffffffffu, p[h], off);
    if (lane == 0)
#pragma unroll
        for (int h = 0; h < 8; ++h) part[warp][h] = p[h];
    __syncthreads();

    if (tid < 8) {
        float s = 0.0f;
#pragma unroll
        for (int g = 0; g < 16; ++g) s += part[g][tid];
        g_bias16[tid * 225 + t] = 16.0f / (1.0f + expf(-s));
    }
    if (blockIdx.x == 0 && tid < 8)
        g_scale[tid] = expf(fminf(ls[tid], 4.6051701860f));
}

// ============================================================
// Kernel 0b: convert x and weights to tf32 bits (once)
// grid 16640 x 256
// ============================================================
__global__ void swin_cvt_kernel(const float* __restrict__ x,
                                const float* __restrict__ Wq,
                                const float* __restrict__ Wk,
                                const float* __restrict__ Wv,
                                const float* __restrict__ Wo)
{
    const int blk = blockIdx.x;
    const int tid = threadIdx.x;
    if (blk < 16384) {
        int i4 = blk * 256 + tid;
        float4 v = ((const float4*)x)[i4];
        ((uint4*)g_xtf)[i4] = make_uint4(f2tf(v.x), f2tf(v.y), f2tf(v.z), f2tf(v.w));
    } else {
        int r  = blk - 16384;            // 0..255 (64 blocks per matrix)
        int m  = r >> 6;
        int i4 = (r & 63) * 256 + tid;
        const float* W = (m == 0) ? Wq : (m == 1) ? Wk : (m == 2) ? Wv : Wo;
        float4 v = ((const float4*)W)[i4];
        ((uint4*)(g_wtf + m * 65536))[i4] =
            make_uint4(f2tf(v.x), f2tf(v.y), f2tf(v.z), f2tf(v.w));
    }
}

// ============================================================
// Kernel 1: QKV projection. grid 512 (2 windows/CTA, M=128), 512 threads.
// warps: mw = warp>>2 (M 32-slice), nw = warp&3 (N 64-slice).
// 3-stage cp.async pipeline over K chunks of 32.
// ============================================================
__global__ void __launch_bounds__(512)
swin_qkv_kernel(const float* __restrict__ bq,
                const float* __restrict__ bk,
                const float* __restrict__ bv)
{
    extern __shared__ unsigned sm[];
    unsigned* Xs = sm;
    unsigned* Wt = sm + NSTG * XBUF;
    unsigned* rowbase = sm + NSTG * (XBUF + WBUF);
    const unsigned smem_base = (unsigned)__cvta_generic_to_shared(sm);

    const int bw   = blockIdx.x;          // 0..511
    const int tid  = threadIdx.x;
    const int warp = tid >> 5;
    const int lane = tid & 31;
    const int g    = lane >> 2;
    const int t    = lane & 3;
    const int mw   = warp >> 2;           // 0..3
    const int nw   = warp & 3;            // 0..3

    if (tid < 128) {
        int wv = bw * 2 + (tid >> 6);
        int b = wv >> 6, wy = (wv >> 3) & 7, wx = wv & 7;
        int tok = tid & 63;
        int sy = ((wy << 3) + (tok >> 3) + 4) & 63;
        int sx = ((wx << 3) + (tok & 7) + 4) & 63;
        rowbase[tid] = ((((b << 6) | sy) << 6) | sx) << 8;
    }
    __syncthreads();

    // per-thread fixed load coordinates
    const int arow  = tid >> 3;           // A rows arow, arow+64
    const int apart = tid & 7;
    const unsigned rb0 = rowbase[arow];
    const unsigned rb1 = rowbase[arow + 64];
    const int bkk   = tid >> 6;           // B rows bkk + 8j
    const int bpart = tid & 63;

#define LOAD_A(kc, st) do {                                                    \
        unsigned d0 = smem_base + (((st) * XBUF + arow * XCH + apart * 4) << 2); \
        cp16(d0, g_xtf + rb0 + (kc) * 32 + apart * 4);                          \
        unsigned d1 = smem_base + (((st) * XBUF + (arow + 64) * XCH + apart * 4) << 2); \
        cp16(d1, g_xtf + rb1 + (kc) * 32 + apart * 4);                          \
    } while (0)

#define LOAD_B(W, kc, st) do {                                                 \
        _Pragma("unroll")                                                      \
        for (int jj = 0; jj < 4; ++jj) {                                       \
            int kk = bkk + jj * 8;                                             \
            unsigned d = smem_base +                                           \
                ((NSTG * XBUF + (st) * WBUF + kk * WST + bpart * 4) << 2);     \
            cp16(d, (W) + (((kc) * 32 + kk) << 8) + bpart * 4);                \
        }                                                                      \
    } while (0)

    const float* Bm[3] = {bq, bk, bv};
    float*       Gm[3] = {g_q, g_k, g_v};

#pragma unroll 1
    for (int m = 0; m < 3; ++m) {
        const unsigned* W = g_wtf + m * 65536;
        float acc[2][8][4];
#pragma unroll
        for (int mt = 0; mt < 2; ++mt)
#pragma unroll
            for (int nt = 0; nt < 8; ++nt)
#pragma unroll
                for (int q = 0; q < 4; ++q) acc[mt][nt][q] = 0.0f;

        LOAD_A(0, 0); LOAD_B(W, 0, 0); cp_commit();
        LOAD_A(1, 1); LOAD_B(W, 1, 1); cp_commit();

#pragma unroll 1
        for (int kc = 0; kc < 8; ++kc) {
            if (kc + 2 < 8) {
                int st = (kc + 2) % 3;
                LOAD_A(kc + 2, st); LOAD_B(W, kc + 2, st);
            }
            cp_commit();
            cp_wait<2>();
            __syncthreads();

            const unsigned* XsS = Xs + (kc % 3) * XBUF;
            const unsigned* WtS = Wt + (kc % 3) * WBUF;
#pragma unroll
            for (int ks = 0; ks < 4; ++ks) {
                const int kb = ks * 8;
                unsigned a[2][4];
#pragma unroll
                for (int mt = 0; mt < 2; ++mt) {
                    const unsigned* ar = XsS + (mw * 32 + mt * 16 + g) * XCH + kb + t;
                    a[mt][0] = ar[0];
                    a[mt][1] = ar[8 * XCH];
                    a[mt][2] = ar[4];
                    a[mt][3] = ar[8 * XCH + 4];
                }
                unsigned bf[8][2];
#pragma unroll
                for (int nt = 0; nt < 8; ++nt) {
                    const unsigned* br = WtS + (kb + t) * WST + nw * 64 + nt * 8 + g;
                    bf[nt][0] = br[0];
                    bf[nt][1] = br[4 * WST];
                }
#pragma unroll
                for (int mt = 0; mt < 2; ++mt)
#pragma unroll
                    for (int nt = 0; nt < 8; ++nt)
                        mma8(acc[mt][nt], a[mt], bf[nt]);
            }
            __syncthreads();
        }

        // ---- epilogue ----
        float2 bb[8];
#pragma unroll
        for (int nt = 0; nt < 8; ++nt)
            bb[nt] = *(const float2*)(Bm[m] + nw * 64 + nt * 8 + 2 * t);
#pragma unroll
        for (int mt = 0; mt < 2; ++mt)
#pragma unroll
            for (int nt = 0; nt < 8; ++nt) {
                acc[mt][nt][0] += bb[nt].x;  acc[mt][nt][1] += bb[nt].y;
                acc[mt][nt][2] += bb[nt].x;  acc[mt][nt][3] += bb[nt].y;
            }

        if (m < 2) {
#pragma unroll
            for (int mt = 0; mt < 2; ++mt)
#pragma unroll
                for (int rh = 0; rh < 2; ++rh)
#pragma unroll
                    for (int hh = 0; hh < 2; ++hh) {
                        float s = 0.0f;
#pragma unroll
                        for (int k2 = 0; k2 < 4; ++k2) {
                            int nt = hh * 4 + k2;
                            s += acc[mt][nt][rh * 2]     * acc[mt][nt][rh * 2]
                               + acc[mt][nt][rh * 2 + 1] * acc[mt][nt][rh * 2 + 1];
                        }
                        s += __shfl_xor_sync(0xffffffffu, s, 1);
                        s += __shfl_xor_sync(0xffffffffu, s, 2);
                        float inv = 1.0f / fmaxf(sqrtf(s), 1e-12f);
#pragma unroll
                        for (int k2 = 0; k2 < 4; ++k2) {
                            int nt = hh * 4 + k2;
                            acc[mt][nt][rh * 2]     *= inv;
                            acc[mt][nt][rh * 2 + 1] *= inv;
                        }
                    }
        }

        float* G = Gm[m];
#pragma unroll
        for (int mt = 0; mt < 2; ++mt)
#pragma unroll
            for (int rh = 0; rh < 2; ++rh)
#pragma unroll
                for (int nt = 0; nt < 8; ++nt) {
                    int n    = mw * 32 + mt * 16 + rh * 8 + g;
                    int win  = bw * 2 + (n >> 6);
                    int tok  = n & 63;
                    int col  = nw * 64 + nt * 8 + 2 * t;
                    int head = col >> 5;
                    int d    = col & 31;
                    *(float2*)(G + (((win << 3) | head) << 11) + (tok << 5) + d) =
                        make_float2(acc[mt][nt][rh * 2], acc[mt][nt][rh * 2 + 1]);
                }
    }
#undef LOAD_A
#undef LOAD_B
}

// ============================================================
// Kernel 2: per (window, head) attention, f32x2 packed math.
// grid (1024, 8), 64 threads.  writes g_ao as tf32 bits.
// ============================================================
__global__ void __launch_bounds__(64)
swin_attn_kernel()
{
    __shared__ float ks[NTOK * HD];
    __shared__ float vs[NTOK * HD];
    __shared__ float ps[NTOK * 65];
    __shared__ float bs[225];

    const int w   = blockIdx.x;
    const int h   = blockIdx.y;
    const int tid = threadIdx.x;
    const int base = ((w << 3) | h) << 11;

    const float4* k4 = (const float4*)(g_k + base);
    const float4* v4 = (const float4*)(g_v + base);
#pragma unroll
    for (int it = 0; it < 8; ++it) {
        int idx = tid + it * 64;
        ((float4*)ks)[idx] = k4[idx];
        ((float4*)vs)[idx] = v4[idx];
    }
    for (int idx = tid; idx < 225; idx += 64) bs[idx] = g_bias16[h * 225 + idx];

    u64 qp[16];
    const u64* q8 = (const u64*)(g_q + base + tid * HD);
#pragma unroll
    for (int it = 0; it < 16; ++it) qp[it] = q8[it];
    __syncthreads();

    const float sc = g_scale[h];
    const int wy = (w >> 3) & 7, wx = w & 7;
    const int ty = tid >> 3,     tx = tid & 7;
    const bool mh = (wy == 7), mw = (wx == 7);
    const bool tyl = (ty < 4), txl = (tx < 4);

    float mx = -1e30f;
    for (int m = 0; m < 64; ++m) {
        const u64* kp = (const u64*)(ks + m * 32);
        u64 a0 = 0, a1 = 0, a2 = 0, a3 = 0;
#pragma unroll
        for (int i = 0; i < 4; ++i) {
            fma2(a0, qp[i * 4],     kp[i * 4]);
            fma2(a1, qp[i * 4 + 1], kp[i * 4 + 1]);
            fma2(a2, qp[i * 4 + 2], kp[i * 4 + 2]);
            fma2(a3, qp[i * 4 + 3], kp[i * 4 + 3]);
        }
        u64 s2 = add2(add2(a0, a1), add2(a2, a3));
        float lo, hi;
        unpack2(s2, lo, hi);
        float dot = lo + hi;

        int my = m >> 3, mxc = m & 7;
        float l = dot * sc + bs[(ty - my + 7) * 15 + (tx - mxc + 7)];
        if (mh && (tyl != (my < 4)))  l -= 100.0f;
        if (mw && (txl != (mxc < 4))) l -= 100.0f;
        ps[tid * 65 + m] = l;
        mx = fmaxf(mx, l);
    }

    float sum = 0.0f;
    for (int m = 0; m < 64; ++m) {
        float e = __expf(ps[tid * 65 + m] - mx);
        ps[tid * 65 + m] = e;
        sum += e;
    }
    const float inv = 1.0f / sum;

    u64 op[16];
#pragma unroll
    for (int i = 0; i < 16; ++i) op[i] = 0;
    for (int m = 0; m < 64; ++m) {
        u64 pp = bcast2(ps[tid * 65 + m]);
        const u64* vp = (const u64*)(vs + m * 32);
#pragma unroll
        for (int i = 0; i < 16; ++i) fma2(op[i], pp, vp[i]);
    }

    unsigned* dst = g_ao + (((w << 6) | tid) << 8) + h * HD;
#pragma unroll
    for (int it = 0; it < 8; ++it) {
        float f0, f1, f2v, f3;
        unpack2(op[it * 2],     f0, f1);
        unpack2(op[it * 2 + 1], f2v, f3);
        ((uint4*)dst)[it] = make_uint4(f2tf(f0 * inv), f2tf(f1 * inv),
                                       f2tf(f2v * inv), f2tf(f3 * inv));
    }
}

// ============================================================
// Kernel 3: output projection + inverse window/roll scatter.
// grid 512, 512 threads, same pipeline as K1 (A = g_ao, contiguous rows).
// ============================================================
__global__ void __launch_bounds__(512)
swin_proj_kernel(const float* __restrict__ bo, float* __restrict__ out)
{
    extern __shared__ unsigned sm[];
    unsigned* Xs = sm;
    unsigned* Wt = sm + NSTG * XBUF;
    const unsigned smem_base = (unsigned)__cvta_generic_to_shared(sm);

    const int bw   = blockIdx.x;
    const int tid  = threadIdx.x;
    const int warp = tid >> 5;
    const int lane = tid & 31;
    const int g    = lane >> 2;
    const int t    = lane & 3;
    const int mw   = warp >> 2;
    const int nw   = warp & 3;

    const int arow  = tid >> 3;
    const int apart = tid & 7;
    const int bkk   = tid >> 6;
    const int bpart = tid & 63;
    const unsigned* W = g_wtf + 3 * 65536;
    const unsigned* Abase = g_ao + ((bw * 128) << 8);

#define LOAD_A(kc, st) do {                                                    \
        unsigned d0 = smem_base + (((st) * XBUF + arow * XCH + apart * 4) << 2); \
        cp16(d0, Abase + (arow << 8) + (kc) * 32 + apart * 4);                  \
        unsigned d1 = smem_base + (((st) * XBUF + (arow + 64) * XCH + apart * 4) << 2); \
        cp16(d1, Abase + ((arow + 64) << 8) + (kc) * 32 + apart * 4);           \
    } while (0)

#define LOAD_B(kc, st) do {                                                    \
        _Pragma("unroll")                                                      \
        for (int jj = 0; jj < 4; ++jj) {                                       \
            int kk = bkk + jj * 8;                                             \
            unsigned d = smem_base +                                           \
                ((NSTG * XBUF + (st) * WBUF + kk * WST + bpart * 4) << 2);     \
            cp16(d, W + (((kc) * 32 + kk) << 8) + bpart * 4);                  \
        }                                                                      \
    } while (0)

    float acc[2][8][4];
#pragma unroll
    for (int mt = 0; mt < 2; ++mt)
#pragma unroll
        for (int nt = 0; nt < 8; ++nt)
#pragma unroll
            for (int q = 0; q < 4; ++q) acc[mt][nt][q] = 0.0f;

    LOAD_A(0, 0); LOAD_B(0, 0); cp_commit();
    LOAD_A(1, 1); LOAD_B(1, 1); cp_commit();

#pragma unroll 1
    for (int kc = 0; kc < 8; ++kc) {
        if (kc + 2 < 8) {
            int st = (kc + 2) % 3;
            LOAD_A(kc + 2, st); LOAD_B(kc + 2, st);
        }
        cp_commit();
        cp_wait<2>();
        __syncthreads();

        const unsigned* XsS = Xs + (kc % 3) * XBUF;
        const unsigned* WtS = Wt + (kc % 3) * WBUF;
#pragma unroll
        for (int ks = 0; ks < 4; ++ks) {
            const int kb = ks * 8;
            unsigned a[2][4];
#pragma unroll
            for (int mt = 0; mt < 2; ++mt) {
                const unsigned* ar = XsS + (mw * 32 + mt * 16 + g) * XCH + kb + t;
                a[mt][0] = ar[0];
                a[mt][1] = ar[8 * XCH];
                a[mt][2] = ar[4];
                a[mt][3] = ar[8 * XCH + 4];
            }
            unsigned bf[8][2];
#pragma unroll
            for (int nt = 0; nt < 8; ++nt) {
                const unsigned* br = WtS + (kb + t) * WST + nw * 64 + nt * 8 + g;
                bf[nt][0] = br[0];
                bf[nt][1] = br[4 * WST];
            }
#pragma unroll
            for (int mt = 0; mt < 2; ++mt)
#pragma unroll
                for (int nt = 0; nt < 8; ++nt)
                    mma8(acc[mt][nt], a[mt], bf[nt]);
        }
        __syncthreads();
    }

    float2 bb[8];
#pragma unroll
    for (int nt = 0; nt < 8; ++nt)
        bb[nt] = *(const float2*)(bo + nw * 64 + nt * 8 + 2 * t);

#pragma unroll
    for (int mt = 0; mt < 2; ++mt)
#pragma unroll
        for (int rh = 0; rh < 2; ++rh)
#pragma unroll
            for (int nt = 0; nt < 8; ++nt) {
                int n   = mw * 32 + mt * 16 + rh * 8 + g;
                int wv  = bw * 2 + (n >> 6);
                int tok = n & 63;
                int b   = wv >> 6, wy = (wv >> 3) & 7, wx = wv & 7;
                int y   = ((wy << 3) + (tok >> 3) + 4) & 63;
                int xc  = ((wx << 3) + (tok & 7) + 4) & 63;
                int col = nw * 64 + nt * 8 + 2 * t;
                *(float2*)(out + (((b << 6) | y) << 14) + (xc << 8) + col) =
                    make_float2(acc[mt][nt][rh * 2] + bb[nt].x,
                                acc[mt][nt][rh * 2 + 1] + bb[nt].y);
            }
#undef LOAD_A
#undef LOAD_B
}

// ============================================================
extern "C" void kernel_launch(void* const* d_in, const int* in_sizes, int n_in,
                              void* d_out, int out_size)
{
    const float* x  = (const float*)d_in[0];
    const float* Wq = (const float*)d_in[1];
    const float* bq = (const float*)d_in[2];
    const float* Wk = (const float*)d_in[3];
    const float* bk = (const float*)d_in[4];
    const float* Wv = (const float*)d_in[5];
    const float* bv = (const float*)d_in[6];
    const float* Wo = (const float*)d_in[7];
    const float* bo = (const float*)d_in[8];
    const float* ls = (const float*)d_in[9];
    const float* w1 = (const float*)d_in[10];
    const float* b1 = (const float*)d_in[11];
    const float* w2 = (const float*)d_in[12];
    float* out = (float*)d_out;

    cudaFuncSetAttribute(swin_qkv_kernel,
                         cudaFuncAttributeMaxDynamicSharedMemorySize, G_SMEM);
    cudaFuncSetAttribute(swin_proj_kernel,
                         cudaFuncAttributeMaxDynamicSharedMemorySize, G_SMEM);

    swin_bias_kernel<<<225, 512>>>(ls, w1, b1, w2);
    swin_cvt_kernel<<<16640, 256>>>(x, Wq, Wk, Wv, Wo);
    swin_qkv_kernel<<<512, 512, G_SMEM>>>(bq, bk, bv);
    swin_attn_kernel<<<dim3(NWIN, NHEAD), 64>>>();
    swin_proj_kernel<<<512, 512, G_SMEM>>>(bo, out);
}